// round 1
// baseline (speedup 1.0000x reference)
#include <cuda_runtime.h>

#define H  2048
#define SW 256
#define SD 200
#define VOCAB 128
#define O  128
#define IH (H + SW)   // 2304

// ---- scratch (device globals; no allocation allowed) ----
__device__ float g_logits[3];
__device__ float g_sin[SW];
__device__ float g_stacktop[SW];
__device__ float g_hnew[H];

// ---- block-wide sum reduction (blockDim.x <= 1024, multiple of 32) ----
__device__ __forceinline__ float blockReduceSum(float v) {
    __shared__ float sm[32];
    int lane = threadIdx.x & 31;
    int wid  = threadIdx.x >> 5;
    #pragma unroll
    for (int o = 16; o > 0; o >>= 1) v += __shfl_down_sync(0xffffffffu, v, o);
    if (lane == 0) sm[wid] = v;
    __syncthreads();
    int nw = blockDim.x >> 5;
    v = (threadIdx.x < nw) ? sm[threadIdx.x] : 0.0f;
    if (wid == 0) {
        #pragma unroll
        for (int o = 16; o > 0; o >>= 1) v += __shfl_down_sync(0xffffffffu, v, o);
    }
    return v; // valid in thread 0
}

// K1: controller logits (3 dots of length H)
__global__ void ctrl_kernel(const float* __restrict__ hidden,
                            const float* __restrict__ Wc,
                            const float* __restrict__ bc) {
    int row = blockIdx.x;
    const float4* w  = reinterpret_cast<const float4*>(Wc + (size_t)row * H);
    const float4* h4 = reinterpret_cast<const float4*>(hidden);
    float s = 0.f;
    for (int k = threadIdx.x; k < H / 4; k += blockDim.x) {
        float4 a = w[k], b = h4[k];
        s += a.x * b.x + a.y * b.y + a.z * b.z + a.w * b.w;
    }
    s = blockReduceSum(s);
    if (threadIdx.x == 0) g_logits[row] = s + bc[row];
}

// K2: s_in = tanh(Ws @ hidden + bs), 256 rows
__global__ void sin_kernel(const float* __restrict__ hidden,
                           const float* __restrict__ Ws,
                           const float* __restrict__ bs) {
    int row = blockIdx.x;
    const float4* w  = reinterpret_cast<const float4*>(Ws + (size_t)row * H);
    const float4* h4 = reinterpret_cast<const float4*>(hidden);
    float s = 0.f;
    for (int k = threadIdx.x; k < H / 4; k += blockDim.x) {
        float4 a = w[k], b = h4[k];
        s += a.x * b.x + a.y * b.y + a.z * b.z + a.w * b.w;
    }
    s = blockReduceSum(s);
    if (threadIdx.x == 0) g_sin[row] = tanhf(s + bs[row]);
}

// K3: differentiable stack update; writes new_stack to d_out and stack_top scratch
__global__ void stack_kernel(const float* __restrict__ stack,
                             float* __restrict__ out_stack) {
    int d = blockIdx.x;       // depth 0..SD-1
    int w = threadIdx.x;      // width 0..SW-1
    float l0 = g_logits[0], l1 = g_logits[1], l2 = g_logits[2];
    float m  = fmaxf(l0, fmaxf(l1, l2));
    float e0 = __expf(l0 - m), e1 = __expf(l1 - m), e2 = __expf(l2 - m);
    float inv = 1.0f / (e0 + e1 + e2);
    float a_push = e0 * inv, a_pop = e1 * inv, a_noop = e2 * inv;

    float cur  = stack[d * SW + w];
    float down = (d < SD - 1) ? stack[(d + 1) * SW + w] : 0.0f;
    float up   = (d == 0) ? g_sin[w] : stack[(d - 1) * SW + w];
    float nv = a_noop * cur + a_push * up + a_pop * down;
    out_stack[d * SW + w] = nv;
    if (d == 0) g_stacktop[w] = nv;
}

// K4: fused GRU step. One block per hidden index i: six row-dots + gate math.
__global__ void gru_kernel(const float* __restrict__ hidden,
                           const int*   __restrict__ inp,
                           const float* __restrict__ emb,
                           const float* __restrict__ W_ih,
                           const float* __restrict__ b_ih,
                           const float* __restrict__ W_hh,
                           const float* __restrict__ b_hh,
                           float* __restrict__ out_h) {
    int i = blockIdx.x;
    const float* x = emb + (size_t)inp[0] * H;
    const float4* x4  = reinterpret_cast<const float4*>(x);
    const float4* h4  = reinterpret_cast<const float4*>(hidden);
    const float4* st4 = reinterpret_cast<const float4*>(g_stacktop);

    const float4* wi_r = reinterpret_cast<const float4*>(W_ih + (size_t)i * IH);
    const float4* wi_z = reinterpret_cast<const float4*>(W_ih + (size_t)(H + i) * IH);
    const float4* wi_n = reinterpret_cast<const float4*>(W_ih + (size_t)(2 * H + i) * IH);
    const float4* wh_r = reinterpret_cast<const float4*>(W_hh + (size_t)i * H);
    const float4* wh_z = reinterpret_cast<const float4*>(W_hh + (size_t)(H + i) * H);
    const float4* wh_n = reinterpret_cast<const float4*>(W_hh + (size_t)(2 * H + i) * H);

    float ar = 0.f, az = 0.f, an = 0.f;  // W_ih parts
    float gr = 0.f, gz = 0.f, gn = 0.f;  // W_hh parts

    // x-part of gi (cols 0..H-1 of W_ih rows) and all of gh
    for (int k = threadIdx.x; k < H / 4; k += blockDim.x) {
        float4 xv = x4[k];
        float4 a;
        a = wi_r[k]; ar += a.x*xv.x + a.y*xv.y + a.z*xv.z + a.w*xv.w;
        a = wi_z[k]; az += a.x*xv.x + a.y*xv.y + a.z*xv.z + a.w*xv.w;
        a = wi_n[k]; an += a.x*xv.x + a.y*xv.y + a.z*xv.z + a.w*xv.w;
        float4 hv = h4[k];
        a = wh_r[k]; gr += a.x*hv.x + a.y*hv.y + a.z*hv.z + a.w*hv.w;
        a = wh_z[k]; gz += a.x*hv.x + a.y*hv.y + a.z*hv.z + a.w*hv.w;
        a = wh_n[k]; gn += a.x*hv.x + a.y*hv.y + a.z*hv.z + a.w*hv.w;
    }
    // stack_top part of gi (cols H..H+SW-1)
    for (int k = threadIdx.x; k < SW / 4; k += blockDim.x) {
        float4 sv = st4[k];
        float4 a;
        a = wi_r[H / 4 + k]; ar += a.x*sv.x + a.y*sv.y + a.z*sv.z + a.w*sv.w;
        a = wi_z[H / 4 + k]; az += a.x*sv.x + a.y*sv.y + a.z*sv.z + a.w*sv.w;
        a = wi_n[H / 4 + k]; an += a.x*sv.x + a.y*sv.y + a.z*sv.z + a.w*sv.w;
    }

    // combined 6-value reduction
    __shared__ float sm[8][6];
    int lane = threadIdx.x & 31, wid = threadIdx.x >> 5;
    #pragma unroll
    for (int o = 16; o > 0; o >>= 1) {
        ar += __shfl_down_sync(0xffffffffu, ar, o);
        az += __shfl_down_sync(0xffffffffu, az, o);
        an += __shfl_down_sync(0xffffffffu, an, o);
        gr += __shfl_down_sync(0xffffffffu, gr, o);
        gz += __shfl_down_sync(0xffffffffu, gz, o);
        gn += __shfl_down_sync(0xffffffffu, gn, o);
    }
    if (lane == 0) {
        sm[wid][0] = ar; sm[wid][1] = az; sm[wid][2] = an;
        sm[wid][3] = gr; sm[wid][4] = gz; sm[wid][5] = gn;
    }
    __syncthreads();
    if (threadIdx.x == 0) {
        float AR = 0, AZ = 0, AN = 0, GR = 0, GZ = 0, GN = 0;
        int nw = blockDim.x >> 5;
        #pragma unroll
        for (int wI = 0; wI < 8; wI++) {
            if (wI < nw) {
                AR += sm[wI][0]; AZ += sm[wI][1]; AN += sm[wI][2];
                GR += sm[wI][3]; GZ += sm[wI][4]; GN += sm[wI][5];
            }
        }
        float gir = AR + b_ih[i],          ghr = GR + b_hh[i];
        float giz = AZ + b_ih[H + i],      ghz = GZ + b_hh[H + i];
        float gin = AN + b_ih[2 * H + i],  ghn = GN + b_hh[2 * H + i];
        float r = 1.0f / (1.0f + expf(-(gir + ghr)));
        float z = 1.0f / (1.0f + expf(-(giz + ghz)));
        float n = tanhf(gin + r * ghn);
        float hn = (1.0f - z) * n + z * hidden[i];
        out_h[i]  = hn;
        g_hnew[i] = hn;
    }
}

// K5: decoder out = Wd @ h_new + bd
__global__ void dec_kernel(const float* __restrict__ Wd,
                           const float* __restrict__ bd,
                           float* __restrict__ out_o) {
    int row = blockIdx.x;
    const float4* w  = reinterpret_cast<const float4*>(Wd + (size_t)row * H);
    const float4* h4 = reinterpret_cast<const float4*>(g_hnew);
    float s = 0.f;
    for (int k = threadIdx.x; k < H / 4; k += blockDim.x) {
        float4 a = w[k], b = h4[k];
        s += a.x * b.x + a.y * b.y + a.z * b.z + a.w * b.w;
    }
    s = blockReduceSum(s);
    if (threadIdx.x == 0) out_o[row] = s + bd[row];
}

extern "C" void kernel_launch(void* const* d_in, const int* in_sizes, int n_in,
                              void* d_out, int out_size) {
    const int*   inp    = (const int*)  d_in[0];
    const float* hidden = (const float*)d_in[1];
    const float* stack  = (const float*)d_in[2];
    const float* emb    = (const float*)d_in[3];
    const float* Wc     = (const float*)d_in[4];
    const float* bc     = (const float*)d_in[5];
    const float* Ws     = (const float*)d_in[6];
    const float* bs     = (const float*)d_in[7];
    const float* W_ih   = (const float*)d_in[8];
    const float* b_ih   = (const float*)d_in[9];
    const float* W_hh   = (const float*)d_in[10];
    const float* b_hh   = (const float*)d_in[11];
    const float* Wd     = (const float*)d_in[12];
    const float* bd     = (const float*)d_in[13];

    float* out       = (float*)d_out;
    float* out_o     = out;            // (1,O)        : 128
    float* out_h     = out + O;        // (1,1,H)      : 2048
    float* out_stack = out + O + H;    // (1,SD,SW)    : 51200

    ctrl_kernel <<<3, 256>>>(hidden, Wc, bc);
    sin_kernel  <<<SW, 256>>>(hidden, Ws, bs);
    stack_kernel<<<SD, SW>>>(stack, out_stack);
    gru_kernel  <<<H, 256>>>(hidden, inp, emb, W_ih, b_ih, W_hh, b_hh, out_h);
    dec_kernel  <<<O, 256>>>(Wd, bd, out_o);
}

// round 2
// speedup vs baseline: 1.0009x; 1.0009x over previous
#include <cuda_runtime.h>

#define H  2048
#define SW 256
#define SD 200
#define O  128
#define IH (H + SW)   // 2304

// ---- scratch (device globals; no allocation allowed) ----
__device__ float g_probs[3];     // softmax(push,pop,noop)
__device__ float g_sin[SW];      // tanh(Ws@h+bs)
__device__ float g_stacktop[SW]; // new stack row 0
__device__ float g_hnew[H];      // GRU output

// =====================================================================
// K1: prologue — ctrl logits (redundant per block) + s_in row + stack_top
// grid = SW blocks, 256 threads. Each block: 4 dots of length H.
// =====================================================================
__global__ void __launch_bounds__(256) prologue_kernel(
    const float* __restrict__ hidden,
    const float* __restrict__ Wc, const float* __restrict__ bc,
    const float* __restrict__ Ws, const float* __restrict__ bs,
    const float* __restrict__ stack)
{
    int w = blockIdx.x;
    const float4* h4  = reinterpret_cast<const float4*>(hidden);
    const float4* c0p = reinterpret_cast<const float4*>(Wc);
    const float4* c1p = reinterpret_cast<const float4*>(Wc + H);
    const float4* c2p = reinterpret_cast<const float4*>(Wc + 2 * H);
    const float4* wsp = reinterpret_cast<const float4*>(Ws + (size_t)w * H);

    float c0 = 0.f, c1 = 0.f, c2 = 0.f, s = 0.f;
    #pragma unroll 2
    for (int k = threadIdx.x; k < H / 4; k += 256) {
        float4 hv = h4[k];
        float4 a;
        a = c0p[k]; c0 += a.x*hv.x + a.y*hv.y + a.z*hv.z + a.w*hv.w;
        a = c1p[k]; c1 += a.x*hv.x + a.y*hv.y + a.z*hv.z + a.w*hv.w;
        a = c2p[k]; c2 += a.x*hv.x + a.y*hv.y + a.z*hv.z + a.w*hv.w;
        a = wsp[k]; s  += a.x*hv.x + a.y*hv.y + a.z*hv.z + a.w*hv.w;
    }

    __shared__ float sm[8][4];
    int lane = threadIdx.x & 31, wid = threadIdx.x >> 5;
    #pragma unroll
    for (int o = 16; o > 0; o >>= 1) {
        c0 += __shfl_down_sync(0xffffffffu, c0, o);
        c1 += __shfl_down_sync(0xffffffffu, c1, o);
        c2 += __shfl_down_sync(0xffffffffu, c2, o);
        s  += __shfl_down_sync(0xffffffffu, s,  o);
    }
    if (lane == 0) { sm[wid][0]=c0; sm[wid][1]=c1; sm[wid][2]=c2; sm[wid][3]=s; }
    __syncthreads();
    if (threadIdx.x == 0) {
        float L0=0, L1=0, L2=0, S=0;
        #pragma unroll
        for (int i = 0; i < 8; i++) { L0+=sm[i][0]; L1+=sm[i][1]; L2+=sm[i][2]; S+=sm[i][3]; }
        L0 += bc[0]; L1 += bc[1]; L2 += bc[2];
        float m  = fmaxf(L0, fmaxf(L1, L2));
        float e0 = __expf(L0 - m), e1 = __expf(L1 - m), e2 = __expf(L2 - m);
        float inv = 1.0f / (e0 + e1 + e2);
        float p_push = e0 * inv, p_pop = e1 * inv, p_noop = e2 * inv;

        float sin_v = tanhf(S + bs[w]);
        g_sin[w] = sin_v;
        // stack_top[w] = noop*stack[0,w] + push*s_in[w] + pop*stack[1,w]
        g_stacktop[w] = p_noop * stack[w] + p_push * sin_v + p_pop * stack[SW + w];
        if (w == 0) { g_probs[0] = p_push; g_probs[1] = p_pop; g_probs[2] = p_noop; }
    }
}

// =====================================================================
// K2: fused GRU GEMV. One block per hidden index i, 512 threads,
// one front-batched 8-load iteration per thread. r/z gates use fused
// concatenated dots (gi+gh in one accumulator); n keeps gin/ghn split.
// =====================================================================
__global__ void __launch_bounds__(512) gru_kernel(
    const float* __restrict__ hidden,
    const int*   __restrict__ inp,
    const float* __restrict__ emb,
    const float* __restrict__ W_ih, const float* __restrict__ b_ih,
    const float* __restrict__ W_hh, const float* __restrict__ b_hh,
    float* __restrict__ out_h)
{
    int i = blockIdx.x;
    int t = threadIdx.x;
    const float* x = emb + (size_t)inp[0] * H;
    const float4* x4  = reinterpret_cast<const float4*>(x);
    const float4* h4  = reinterpret_cast<const float4*>(hidden);
    const float4* st4 = reinterpret_cast<const float4*>(g_stacktop);

    const float4* wi_r = reinterpret_cast<const float4*>(W_ih + (size_t)i * IH);
    const float4* wi_z = reinterpret_cast<const float4*>(W_ih + (size_t)(H + i) * IH);
    const float4* wi_n = reinterpret_cast<const float4*>(W_ih + (size_t)(2 * H + i) * IH);
    const float4* wh_r = reinterpret_cast<const float4*>(W_hh + (size_t)i * H);
    const float4* wh_z = reinterpret_cast<const float4*>(W_hh + (size_t)(H + i) * H);
    const float4* wh_n = reinterpret_cast<const float4*>(W_hh + (size_t)(2 * H + i) * H);

    float acc_r = 0.f, acc_z = 0.f, acc_gin = 0.f, acc_ghn = 0.f;

    // H/4 = 512 float4 columns, exactly one per thread — all 8 loads independent.
    {
        int k = t;
        float4 xv = x4[k];
        float4 hv = h4[k];
        float4 a0 = wi_r[k];
        float4 a1 = wh_r[k];
        float4 a2 = wi_z[k];
        float4 a3 = wh_z[k];
        float4 a4 = wi_n[k];
        float4 a5 = wh_n[k];
        acc_r   += a0.x*xv.x + a0.y*xv.y + a0.z*xv.z + a0.w*xv.w;
        acc_r   += a1.x*hv.x + a1.y*hv.y + a1.z*hv.z + a1.w*hv.w;
        acc_z   += a2.x*xv.x + a2.y*xv.y + a2.z*xv.z + a2.w*xv.w;
        acc_z   += a3.x*hv.x + a3.y*hv.y + a3.z*hv.z + a3.w*hv.w;
        acc_gin += a4.x*xv.x + a4.y*xv.y + a4.z*xv.z + a4.w*xv.w;
        acc_ghn += a5.x*hv.x + a5.y*hv.y + a5.z*hv.z + a5.w*hv.w;
    }
    // stack_top segment: SW/4 = 64 float4 columns, threads 0..63
    if (t < SW / 4) {
        int k = t;
        float4 sv = st4[k];
        float4 b0 = wi_r[H / 4 + k];
        float4 b1 = wi_z[H / 4 + k];
        float4 b2 = wi_n[H / 4 + k];
        acc_r   += b0.x*sv.x + b0.y*sv.y + b0.z*sv.z + b0.w*sv.w;
        acc_z   += b1.x*sv.x + b1.y*sv.y + b1.z*sv.z + b1.w*sv.w;
        acc_gin += b2.x*sv.x + b2.y*sv.y + b2.z*sv.z + b2.w*sv.w;
    }

    // 4-value reduction across 16 warps
    __shared__ float sm[16][4];
    int lane = t & 31, wid = t >> 5;
    #pragma unroll
    for (int o = 16; o > 0; o >>= 1) {
        acc_r   += __shfl_down_sync(0xffffffffu, acc_r,   o);
        acc_z   += __shfl_down_sync(0xffffffffu, acc_z,   o);
        acc_gin += __shfl_down_sync(0xffffffffu, acc_gin, o);
        acc_ghn += __shfl_down_sync(0xffffffffu, acc_ghn, o);
    }
    if (lane == 0) { sm[wid][0]=acc_r; sm[wid][1]=acc_z; sm[wid][2]=acc_gin; sm[wid][3]=acc_ghn; }
    __syncthreads();
    if (t == 0) {
        float R=0, Z=0, GIN=0, GHN=0;
        #pragma unroll
        for (int wI = 0; wI < 16; wI++) {
            R += sm[wI][0]; Z += sm[wI][1]; GIN += sm[wI][2]; GHN += sm[wI][3];
        }
        float r = 1.0f / (1.0f + expf(-(R + b_ih[i]         + b_hh[i])));
        float z = 1.0f / (1.0f + expf(-(Z + b_ih[H + i]     + b_hh[H + i])));
        float n = tanhf(GIN + b_ih[2 * H + i] + r * (GHN + b_hh[2 * H + i]));
        float hn = (1.0f - z) * n + z * hidden[i];
        out_h[i]  = hn;
        g_hnew[i] = hn;
    }
}

// =====================================================================
// K3: epilogue — blocks [0,O): decoder rows; blocks [O, O+SD): stack update
// =====================================================================
__global__ void __launch_bounds__(256) epilogue_kernel(
    const float* __restrict__ stack,
    const float* __restrict__ Wd, const float* __restrict__ bd,
    float* __restrict__ out_o, float* __restrict__ out_stack)
{
    int b = blockIdx.x;
    if (b < O) {
        // decoder row dot
        const float4* w4 = reinterpret_cast<const float4*>(Wd + (size_t)b * H);
        const float4* h4 = reinterpret_cast<const float4*>(g_hnew);
        float s = 0.f;
        #pragma unroll 2
        for (int k = threadIdx.x; k < H / 4; k += 256) {
            float4 a = w4[k], v = h4[k];
            s += a.x*v.x + a.y*v.y + a.z*v.z + a.w*v.w;
        }
        __shared__ float sm[32];
        int lane = threadIdx.x & 31, wid = threadIdx.x >> 5;
        #pragma unroll
        for (int o = 16; o > 0; o >>= 1) s += __shfl_down_sync(0xffffffffu, s, o);
        if (lane == 0) sm[wid] = s;
        __syncthreads();
        if (threadIdx.x == 0) {
            float S = 0.f;
            #pragma unroll
            for (int wI = 0; wI < 8; wI++) S += sm[wI];
            out_o[b] = S + bd[b];
        }
    } else {
        // stack update for depth d
        int d = b - O;
        int w = threadIdx.x;  // 0..SW-1
        float p_push = g_probs[0], p_pop = g_probs[1], p_noop = g_probs[2];
        float cur  = stack[d * SW + w];
        float down = (d < SD - 1) ? stack[(d + 1) * SW + w] : 0.0f;
        float up   = (d == 0) ? g_sin[w] : stack[(d - 1) * SW + w];
        out_stack[d * SW + w] = p_noop * cur + p_push * up + p_pop * down;
    }
}

extern "C" void kernel_launch(void* const* d_in, const int* in_sizes, int n_in,
                              void* d_out, int out_size) {
    const int*   inp    = (const int*)  d_in[0];
    const float* hidden = (const float*)d_in[1];
    const float* stack  = (const float*)d_in[2];
    const float* emb    = (const float*)d_in[3];
    const float* Wc     = (const float*)d_in[4];
    const float* bc     = (const float*)d_in[5];
    const float* Ws     = (const float*)d_in[6];
    const float* bs     = (const float*)d_in[7];
    const float* W_ih   = (const float*)d_in[8];
    const float* b_ih   = (const float*)d_in[9];
    const float* W_hh   = (const float*)d_in[10];
    const float* b_hh   = (const float*)d_in[11];
    const float* Wd     = (const float*)d_in[12];
    const float* bd     = (const float*)d_in[13];

    float* out       = (float*)d_out;
    float* out_o     = out;            // (1,O)     : 128
    float* out_h     = out + O;        // (1,1,H)   : 2048
    float* out_stack = out + O + H;    // (1,SD,SW) : 51200

    prologue_kernel<<<SW, 256>>>(hidden, Wc, bc, Ws, bs, stack);
    gru_kernel     <<<H, 512>>>(hidden, inp, emb, W_ih, b_ih, W_hh, b_hh, out_h);
    epilogue_kernel<<<O + SD, 256>>>(stack, Wd, bd, out_o, out_stack);
}

// round 3
// speedup vs baseline: 1.1311x; 1.1301x over previous
#include <cuda_runtime.h>

#define H  2048
#define SW 256
#define SD 200
#define O  128
#define IH (H + SW)   // 2304

// ---- scratch (device globals) ----
__device__ float g_logits[3];   // raw ctrl logits
__device__ float g_sin[SW];     // tanh(Ws@h+bs)
__device__ float g_hnew[H];     // GRU output

__device__ __forceinline__ void softmax3(float& pp, float& po, float& pn) {
    float l0 = g_logits[0], l1 = g_logits[1], l2 = g_logits[2];
    float m  = fmaxf(l0, fmaxf(l1, l2));
    float e0 = __expf(l0 - m), e1 = __expf(l1 - m), e2 = __expf(l2 - m);
    float inv = 1.0f / (e0 + e1 + e2);
    pp = e0 * inv; po = e1 * inv; pn = e2 * inv;
}

// =====================================================================
// K1: prologue — 259 independent row-dots of length H.
// blocks 0..2: ctrl logits (raw). blocks 3..258: s_in rows (tanh).
// 256 threads, 2 float4 cols per thread, front-batched.
// =====================================================================
__global__ void __launch_bounds__(256) prologue_kernel(
    const float* __restrict__ hidden,
    const float* __restrict__ Wc, const float* __restrict__ bc,
    const float* __restrict__ Ws, const float* __restrict__ bs)
{
    int b = blockIdx.x;
    int t = threadIdx.x;
    const float* rowp = (b < 3) ? (Wc + (size_t)b * H)
                                : (Ws + (size_t)(b - 3) * H);
    const float4* w4 = reinterpret_cast<const float4*>(rowp);
    const float4* h4 = reinterpret_cast<const float4*>(hidden);

    // front-batched: 4 independent loads
    float4 a0 = w4[t];
    float4 a1 = w4[t + 256];
    float4 h0 = h4[t];
    float4 h1 = h4[t + 256];
    float s = a0.x*h0.x + a0.y*h0.y + a0.z*h0.z + a0.w*h0.w
            + a1.x*h1.x + a1.y*h1.y + a1.z*h1.z + a1.w*h1.w;

    __shared__ float sm[8];
    int lane = t & 31, wid = t >> 5;
    #pragma unroll
    for (int o = 16; o > 0; o >>= 1) s += __shfl_down_sync(0xffffffffu, s, o);
    if (lane == 0) sm[wid] = s;
    __syncthreads();
    if (t == 0) {
        float S = 0.f;
        #pragma unroll
        for (int i = 0; i < 8; i++) S += sm[i];
        if (b < 3) g_logits[b] = S + bc[b];
        else       g_sin[b - 3] = tanhf(S + bs[b - 3]);
    }
}

// =====================================================================
// K2: gru + stack kernel.
// blocks [0,1024): GRU rows i0=2b, i1=2b+1. 512 threads, 1 float4 col each.
// blocks [1024,1124): stack update, 2 depth-rows per block (512 thr).
// =====================================================================
__global__ void __launch_bounds__(512, 2) gru_kernel(
    const float* __restrict__ hidden,
    const int*   __restrict__ inp,
    const float* __restrict__ emb,
    const float* __restrict__ W_ih, const float* __restrict__ b_ih,
    const float* __restrict__ W_hh, const float* __restrict__ b_hh,
    const float* __restrict__ stack,
    float* __restrict__ out_h,
    float* __restrict__ out_stack)
{
    int t = threadIdx.x;

    if (blockIdx.x >= 1024) {
        // ---- stack update: rows d = 2*(b-1024) + (t>>8), col w = t&255 ----
        int d = 2 * (int)(blockIdx.x - 1024) + (t >> 8);
        int w = t & 255;
        float pp, po, pn; softmax3(pp, po, pn);
        float cur  = stack[d * SW + w];
        float down = (d < SD - 1) ? stack[(d + 1) * SW + w] : 0.0f;
        float up   = (d == 0) ? g_sin[w] : stack[(d - 1) * SW + w];
        out_stack[d * SW + w] = pn * cur + pp * up + po * down;
        return;
    }

    // ---- GRU: two hidden rows per block ----
    int i0 = 2 * blockIdx.x;
    int i1 = i0 + 1;
    const float* x = emb + (size_t)inp[0] * H;
    const float4* x4 = reinterpret_cast<const float4*>(x);
    const float4* h4 = reinterpret_cast<const float4*>(hidden);

    const float4* wi_r0 = reinterpret_cast<const float4*>(W_ih + (size_t)i0 * IH);
    const float4* wi_z0 = reinterpret_cast<const float4*>(W_ih + (size_t)(H + i0) * IH);
    const float4* wi_n0 = reinterpret_cast<const float4*>(W_ih + (size_t)(2 * H + i0) * IH);
    const float4* wh_r0 = reinterpret_cast<const float4*>(W_hh + (size_t)i0 * H);
    const float4* wh_z0 = reinterpret_cast<const float4*>(W_hh + (size_t)(H + i0) * H);
    const float4* wh_n0 = reinterpret_cast<const float4*>(W_hh + (size_t)(2 * H + i0) * H);
    const float4* wi_r1 = reinterpret_cast<const float4*>(W_ih + (size_t)i1 * IH);
    const float4* wi_z1 = reinterpret_cast<const float4*>(W_ih + (size_t)(H + i1) * IH);
    const float4* wi_n1 = reinterpret_cast<const float4*>(W_ih + (size_t)(2 * H + i1) * IH);
    const float4* wh_r1 = reinterpret_cast<const float4*>(W_hh + (size_t)i1 * H);
    const float4* wh_z1 = reinterpret_cast<const float4*>(W_hh + (size_t)(H + i1) * H);
    const float4* wh_n1 = reinterpret_cast<const float4*>(W_hh + (size_t)(2 * H + i1) * H);

    float r0 = 0.f, z0 = 0.f, gi_n0 = 0.f, gh_n0 = 0.f;
    float r1 = 0.f, z1 = 0.f, gi_n1 = 0.f, gh_n1 = 0.f;

    int k = t;  // 512 cols, one per thread
    float4 xv = x4[k];
    float4 hv = h4[k];
    {
        float4 a;
        a = wi_r0[k]; r0    += a.x*xv.x + a.y*xv.y + a.z*xv.z + a.w*xv.w;
        a = wh_r0[k]; r0    += a.x*hv.x + a.y*hv.y + a.z*hv.z + a.w*hv.w;
        a = wi_z0[k]; z0    += a.x*xv.x + a.y*xv.y + a.z*xv.z + a.w*xv.w;
        a = wh_z0[k]; z0    += a.x*hv.x + a.y*hv.y + a.z*hv.z + a.w*hv.w;
        a = wi_n0[k]; gi_n0 += a.x*xv.x + a.y*xv.y + a.z*xv.z + a.w*xv.w;
        a = wh_n0[k]; gh_n0 += a.x*hv.x + a.y*hv.y + a.z*hv.z + a.w*hv.w;
        a = wi_r1[k]; r1    += a.x*xv.x + a.y*xv.y + a.z*xv.z + a.w*xv.w;
        a = wh_r1[k]; r1    += a.x*hv.x + a.y*hv.y + a.z*hv.z + a.w*hv.w;
        a = wi_z1[k]; z1    += a.x*xv.x + a.y*xv.y + a.z*xv.z + a.w*xv.w;
        a = wh_z1[k]; z1    += a.x*hv.x + a.y*hv.y + a.z*hv.z + a.w*hv.w;
        a = wi_n1[k]; gi_n1 += a.x*xv.x + a.y*xv.y + a.z*xv.z + a.w*xv.w;
        a = wh_n1[k]; gh_n1 += a.x*hv.x + a.y*hv.y + a.z*hv.z + a.w*hv.w;
    }

    // stack_top segment (cols H..H+SW-1 of W_ih rows), threads 0..63
    if (t < SW / 4) {
        float pp, po, pn; softmax3(pp, po, pn);
        const float4* s0p = reinterpret_cast<const float4*>(stack);
        const float4* s1p = reinterpret_cast<const float4*>(stack + SW);
        const float4* sip = reinterpret_cast<const float4*>(g_sin);
        float4 s0 = s0p[t], s1 = s1p[t], si = sip[t];
        float4 st;
        st.x = pn * s0.x + pp * si.x + po * s1.x;
        st.y = pn * s0.y + pp * si.y + po * s1.y;
        st.z = pn * s0.z + pp * si.z + po * s1.z;
        st.w = pn * s0.w + pp * si.w + po * s1.w;
        int c = H / 4 + t;
        float4 a;
        a = wi_r0[c]; r0    += a.x*st.x + a.y*st.y + a.z*st.z + a.w*st.w;
        a = wi_z0[c]; z0    += a.x*st.x + a.y*st.y + a.z*st.z + a.w*st.w;
        a = wi_n0[c]; gi_n0 += a.x*st.x + a.y*st.y + a.z*st.z + a.w*st.w;
        a = wi_r1[c]; r1    += a.x*st.x + a.y*st.y + a.z*st.z + a.w*st.w;
        a = wi_z1[c]; z1    += a.x*st.x + a.y*st.y + a.z*st.z + a.w*st.w;
        a = wi_n1[c]; gi_n1 += a.x*st.x + a.y*st.y + a.z*st.z + a.w*st.w;
    }

    // ---- 8-value reduction across 16 warps ----
    __shared__ float sm[16][8];
    __shared__ float tot[8];
    int lane = t & 31, wid = t >> 5;
    #pragma unroll
    for (int o = 16; o > 0; o >>= 1) {
        r0    += __shfl_down_sync(0xffffffffu, r0,    o);
        z0    += __shfl_down_sync(0xffffffffu, z0,    o);
        gi_n0 += __shfl_down_sync(0xffffffffu, gi_n0, o);
        gh_n0 += __shfl_down_sync(0xffffffffu, gh_n0, o);
        r1    += __shfl_down_sync(0xffffffffu, r1,    o);
        z1    += __shfl_down_sync(0xffffffffu, z1,    o);
        gi_n1 += __shfl_down_sync(0xffffffffu, gi_n1, o);
        gh_n1 += __shfl_down_sync(0xffffffffu, gh_n1, o);
    }
    if (lane == 0) {
        sm[wid][0] = r0;  sm[wid][1] = z0;  sm[wid][2] = gi_n0; sm[wid][3] = gh_n0;
        sm[wid][4] = r1;  sm[wid][5] = z1;  sm[wid][6] = gi_n1; sm[wid][7] = gh_n1;
    }
    __syncthreads();
    if (t < 8) {
        float v = 0.f;
        #pragma unroll
        for (int j = 0; j < 16; j++) v += sm[j][t];
        tot[t] = v;
    }
    __syncthreads();
    if (t < 2) {
        int i = (t == 0) ? i0 : i1;
        int o4 = 4 * t;
        float R   = tot[o4 + 0], Z = tot[o4 + 1];
        float GIN = tot[o4 + 2], GHN = tot[o4 + 3];
        float r = 1.0f / (1.0f + expf(-(R + b_ih[i] + b_hh[i])));
        float z = 1.0f / (1.0f + expf(-(Z + b_ih[H + i] + b_hh[H + i])));
        float n = tanhf(GIN + b_ih[2 * H + i] + r * (GHN + b_hh[2 * H + i]));
        float hn = (1.0f - z) * n + z * hidden[i];
        out_h[i]  = hn;
        g_hnew[i] = hn;
    }
}

// =====================================================================
// K3: decoder — out = Wd @ h_new + bd. 128 blocks, 256 threads,
// 2 cols/thread front-batched.
// =====================================================================
__global__ void __launch_bounds__(256) dec_kernel(
    const float* __restrict__ Wd, const float* __restrict__ bd,
    float* __restrict__ out_o)
{
    int b = blockIdx.x;
    int t = threadIdx.x;
    const float4* w4 = reinterpret_cast<const float4*>(Wd + (size_t)b * H);
    const float4* h4 = reinterpret_cast<const float4*>(g_hnew);
    float4 a0 = w4[t];
    float4 a1 = w4[t + 256];
    float4 h0 = h4[t];
    float4 h1 = h4[t + 256];
    float s = a0.x*h0.x + a0.y*h0.y + a0.z*h0.z + a0.w*h0.w
            + a1.x*h1.x + a1.y*h1.y + a1.z*h1.z + a1.w*h1.w;

    __shared__ float sm[8];
    int lane = t & 31, wid = t >> 5;
    #pragma unroll
    for (int o = 16; o > 0; o >>= 1) s += __shfl_down_sync(0xffffffffu, s, o);
    if (lane == 0) sm[wid] = s;
    __syncthreads();
    if (t == 0) {
        float S = 0.f;
        #pragma unroll
        for (int i = 0; i < 8; i++) S += sm[i];
        out_o[b] = S + bd[b];
    }
}

extern "C" void kernel_launch(void* const* d_in, const int* in_sizes, int n_in,
                              void* d_out, int out_size) {
    const int*   inp    = (const int*)  d_in[0];
    const float* hidden = (const float*)d_in[1];
    const float* stack  = (const float*)d_in[2];
    const float* emb    = (const float*)d_in[3];
    const float* Wc     = (const float*)d_in[4];
    const float* bc     = (const float*)d_in[5];
    const float* Ws     = (const float*)d_in[6];
    const float* bs     = (const float*)d_in[7];
    const float* W_ih   = (const float*)d_in[8];
    const float* b_ih   = (const float*)d_in[9];
    const float* W_hh   = (const float*)d_in[10];
    const float* b_hh   = (const float*)d_in[11];
    const float* Wd     = (const float*)d_in[12];
    const float* bd     = (const float*)d_in[13];

    float* out       = (float*)d_out;
    float* out_o     = out;            // (1,O)     : 128
    float* out_h     = out + O;        // (1,1,H)   : 2048
    float* out_stack = out + O + H;    // (1,SD,SW) : 51200

    prologue_kernel<<<3 + SW, 256>>>(hidden, Wc, bc, Ws, bs);
    gru_kernel<<<1024 + SD / 2, 512>>>(hidden, inp, emb, W_ih, b_ih,
                                       W_hh, b_hh, stack, out_h, out_stack);
    dec_kernel<<<O, 256>>>(Wd, bd, out_o);
}

// round 4
// speedup vs baseline: 1.2000x; 1.0609x over previous
#include <cuda_runtime.h>

#define H  2048
#define SW 256
#define SD 200
#define O  128
#define IH (H + SW)   // 2304

// ---- scratch (device globals) ----
__device__ float g_logits[3];
__device__ float g_sin[SW];
__device__ float g_pr[H];    // Wih_r[:H]·x + Whh_r·h
__device__ float g_pz[H];
__device__ float g_pgin[H];  // Wih_n[:H]·x
__device__ float g_pghn[H];  // Whh_n·h
__device__ float g_hnew[H];
__device__ int   g_done;

__device__ __forceinline__ float dot4(float4 a, float4 b) {
    return a.x*b.x + a.y*b.y + a.z*b.z + a.w*b.w;
}

__device__ __forceinline__ void softmax3(float& pp, float& po, float& pn) {
    float l0 = g_logits[0], l1 = g_logits[1], l2 = g_logits[2];
    float m  = fmaxf(l0, fmaxf(l1, l2));
    float e0 = __expf(l0 - m), e1 = __expf(l1 - m), e2 = __expf(l2 - m);
    float inv = 1.0f / (e0 + e1 + e2);
    pp = e0 * inv; po = e1 * inv; pn = e2 * inv;
}

// =====================================================================
// K1: blocks [0,2048): GRU main dots (partials). blocks [2048,2307):
// prologue dots (3 ctrl + 256 s_in). 256 threads.
// =====================================================================
__global__ void __launch_bounds__(256) k1_kernel(
    const float* __restrict__ hidden,
    const int*   __restrict__ inp,
    const float* __restrict__ emb,
    const float* __restrict__ W_ih,
    const float* __restrict__ W_hh,
    const float* __restrict__ Wc, const float* __restrict__ bc,
    const float* __restrict__ Ws, const float* __restrict__ bs)
{
    int b = blockIdx.x;
    int t = threadIdx.x;
    const float4* h4 = reinterpret_cast<const float4*>(hidden);
    __shared__ float sm[8][4];
    int lane = t & 31, wid = t >> 5;

    if (b >= 2048) {
        // ---- prologue: one dot of length H ----
        int r = b - 2048;
        const float* rowp = (r < 3) ? (Wc + (size_t)r * H)
                                    : (Ws + (size_t)(r - 3) * H);
        const float4* w4 = reinterpret_cast<const float4*>(rowp);
        float4 a0 = w4[t], a1 = w4[t + 256];
        float4 h0 = h4[t], h1 = h4[t + 256];
        float s = dot4(a0, h0) + dot4(a1, h1);
        #pragma unroll
        for (int o = 16; o > 0; o >>= 1) s += __shfl_down_sync(0xffffffffu, s, o);
        if (lane == 0) sm[wid][0] = s;
        __syncthreads();
        if (t == 0) {
            float S = 0.f;
            #pragma unroll
            for (int j = 0; j < 8; j++) S += sm[j][0];
            if (r < 3) g_logits[r] = S + bc[r];
            else       g_sin[r - 3] = tanhf(S + bs[r - 3]);
            if (r == 0) g_done = 0;   // reset spin counter for K2
        }
        return;
    }

    // ---- GRU main: row i, 6 dots of length H ----
    int i = b;
    const float* x = emb + (size_t)inp[0] * H;
    const float4* x4 = reinterpret_cast<const float4*>(x);
    const float4* wi_r = reinterpret_cast<const float4*>(W_ih + (size_t)i * IH);
    const float4* wi_z = reinterpret_cast<const float4*>(W_ih + (size_t)(H + i) * IH);
    const float4* wi_n = reinterpret_cast<const float4*>(W_ih + (size_t)(2 * H + i) * IH);
    const float4* wh_r = reinterpret_cast<const float4*>(W_hh + (size_t)i * H);
    const float4* wh_z = reinterpret_cast<const float4*>(W_hh + (size_t)(H + i) * H);
    const float4* wh_n = reinterpret_cast<const float4*>(W_hh + (size_t)(2 * H + i) * H);

    float pr = 0.f, pz = 0.f, pgin = 0.f, pghn = 0.f;
    #pragma unroll
    for (int u = 0; u < 2; u++) {
        int k = t + u * 256;
        float4 xv = x4[k];
        float4 hv = h4[k];
        float4 a;
        a = wi_r[k]; pr   += dot4(a, xv);
        a = wh_r[k]; pr   += dot4(a, hv);
        a = wi_z[k]; pz   += dot4(a, xv);
        a = wh_z[k]; pz   += dot4(a, hv);
        a = wi_n[k]; pgin += dot4(a, xv);
        a = wh_n[k]; pghn += dot4(a, hv);
    }

    #pragma unroll
    for (int o = 16; o > 0; o >>= 1) {
        pr   += __shfl_down_sync(0xffffffffu, pr,   o);
        pz   += __shfl_down_sync(0xffffffffu, pz,   o);
        pgin += __shfl_down_sync(0xffffffffu, pgin, o);
        pghn += __shfl_down_sync(0xffffffffu, pghn, o);
    }
    if (lane == 0) { sm[wid][0]=pr; sm[wid][1]=pz; sm[wid][2]=pgin; sm[wid][3]=pghn; }
    __syncthreads();
    if (t < 4) {
        float v = 0.f;
        #pragma unroll
        for (int j = 0; j < 8; j++) v += sm[j][t];
        if      (t == 0) g_pr[i]   = v;
        else if (t == 1) g_pz[i]   = v;
        else if (t == 2) g_pgin[i] = v;
        else             g_pghn[i] = v;
    }
}

// =====================================================================
// K2: 64-thread blocks, all co-resident (2376 blocks = within chip
// residency), so the decoder spin on g_done is deadlock-free.
//   blocks [0,2048):      GRU finish (stack_top dot + gates + h_new)
//   blocks [2048,2248):   stack update (one depth row each)
//   blocks [2248,2376):   decoder rows (spin until g_done == 2048)
// =====================================================================
__global__ void __launch_bounds__(64) k2_kernel(
    const float* __restrict__ hidden,
    const float* __restrict__ W_ih,
    const float* __restrict__ b_ih, const float* __restrict__ b_hh,
    const float* __restrict__ stack,
    const float* __restrict__ Wd, const float* __restrict__ bd,
    float* __restrict__ out_o, float* __restrict__ out_h,
    float* __restrict__ out_stack)
{
    int b = blockIdx.x;
    int t = threadIdx.x;

    if (b < 2048) {
        // ---- GRU finish for row i ----
        int i = b;
        float pp, po, pn; softmax3(pp, po, pn);
        const float4* s0p = reinterpret_cast<const float4*>(stack);
        const float4* s1p = reinterpret_cast<const float4*>(stack + SW);
        const float4* sip = reinterpret_cast<const float4*>(g_sin);
        float4 v0 = s0p[t], v1 = s1p[t], vs = sip[t];
        float4 st;
        st.x = pn*v0.x + pp*vs.x + po*v1.x;
        st.y = pn*v0.y + pp*vs.y + po*v1.y;
        st.z = pn*v0.z + pp*vs.z + po*v1.z;
        st.w = pn*v0.w + pp*vs.w + po*v1.w;

        const float4* wr = reinterpret_cast<const float4*>(W_ih + (size_t)i * IH + H);
        const float4* wz = reinterpret_cast<const float4*>(W_ih + (size_t)(H + i) * IH + H);
        const float4* wn = reinterpret_cast<const float4*>(W_ih + (size_t)(2 * H + i) * IH + H);
        float ar = dot4(wr[t], st);
        float az = dot4(wz[t], st);
        float an = dot4(wn[t], st);

        __shared__ float sm[2][3];
        int lane = t & 31, wid = t >> 5;
        #pragma unroll
        for (int o = 16; o > 0; o >>= 1) {
            ar += __shfl_down_sync(0xffffffffu, ar, o);
            az += __shfl_down_sync(0xffffffffu, az, o);
            an += __shfl_down_sync(0xffffffffu, an, o);
        }
        if (lane == 0) { sm[wid][0] = ar; sm[wid][1] = az; sm[wid][2] = an; }
        __syncthreads();
        if (t == 0) {
            float AR = sm[0][0] + sm[1][0];
            float AZ = sm[0][1] + sm[1][1];
            float AN = sm[0][2] + sm[1][2];
            float r = 1.0f / (1.0f + expf(-(g_pr[i] + AR + b_ih[i] + b_hh[i])));
            float z = 1.0f / (1.0f + expf(-(g_pz[i] + AZ + b_ih[H + i] + b_hh[H + i])));
            float n = tanhf(g_pgin[i] + AN + b_ih[2 * H + i]
                            + r * (g_pghn[i] + b_hh[2 * H + i]));
            float hn = (1.0f - z) * n + z * hidden[i];
            out_h[i]  = hn;
            g_hnew[i] = hn;
            __threadfence();
            atomicAdd(&g_done, 1);
        }
    } else if (b < 2048 + SD) {
        // ---- stack update, depth d ----
        int d = b - 2048;
        float pp, po, pn; softmax3(pp, po, pn);
        const float4* cur4 = reinterpret_cast<const float4*>(stack + (size_t)d * SW);
        float4 cur = cur4[t];
        float4 down = make_float4(0.f, 0.f, 0.f, 0.f);
        if (d < SD - 1)
            down = reinterpret_cast<const float4*>(stack + (size_t)(d + 1) * SW)[t];
        float4 up = (d == 0)
            ? reinterpret_cast<const float4*>(g_sin)[t]
            : reinterpret_cast<const float4*>(stack + (size_t)(d - 1) * SW)[t];
        float4 o;
        o.x = pn*cur.x + pp*up.x + po*down.x;
        o.y = pn*cur.y + pp*up.y + po*down.y;
        o.z = pn*cur.z + pp*up.z + po*down.z;
        o.w = pn*cur.w + pp*up.w + po*down.w;
        reinterpret_cast<float4*>(out_stack)[(size_t)d * (SW / 4) + t] = o;
    } else {
        // ---- decoder row (spin until all h_new ready) ----
        int row = b - (2048 + SD);
        if (t == 0) {
            while (atomicAdd(&g_done, 0) < 2048) __nanosleep(64);
        }
        __syncthreads();

        const float4* w4 = reinterpret_cast<const float4*>(Wd + (size_t)row * H);
        const float4* h4 = reinterpret_cast<const float4*>(g_hnew);
        float s = 0.f;
        #pragma unroll
        for (int u = 0; u < 8; u++) {
            int k = t + u * 64;
            float4 a  = w4[k];
            float4 hv = __ldcg(h4 + k);  // bypass L1: h_new written by other SMs
            s += dot4(a, hv);
        }
        __shared__ float sm2[2];
        int lane = t & 31, wid = t >> 5;
        #pragma unroll
        for (int o = 16; o > 0; o >>= 1) s += __shfl_down_sync(0xffffffffu, s, o);
        if (lane == 0) sm2[wid] = s;
        __syncthreads();
        if (t == 0) out_o[row] = sm2[0] + sm2[1] + bd[row];
    }
}

extern "C" void kernel_launch(void* const* d_in, const int* in_sizes, int n_in,
                              void* d_out, int out_size) {
    const int*   inp    = (const int*)  d_in[0];
    const float* hidden = (const float*)d_in[1];
    const float* stack  = (const float*)d_in[2];
    const float* emb    = (const float*)d_in[3];
    const float* Wc     = (const float*)d_in[4];
    const float* bc     = (const float*)d_in[5];
    const float* Ws     = (const float*)d_in[6];
    const float* bs     = (const float*)d_in[7];
    const float* W_ih   = (const float*)d_in[8];
    const float* b_ih   = (const float*)d_in[9];
    const float* W_hh   = (const float*)d_in[10];
    const float* b_hh   = (const float*)d_in[11];
    const float* Wd     = (const float*)d_in[12];
    const float* bd     = (const float*)d_in[13];

    float* out       = (float*)d_out;
    float* out_o     = out;            // (1,O)     : 128
    float* out_h     = out + O;        // (1,1,H)   : 2048
    float* out_stack = out + O + H;    // (1,SD,SW) : 51200

    k1_kernel<<<2048 + 3 + SW, 256>>>(hidden, inp, emb, W_ih, W_hh,
                                      Wc, bc, Ws, bs);
    k2_kernel<<<2048 + SD + O, 64>>>(hidden, W_ih, b_ih, b_hh, stack,
                                     Wd, bd, out_o, out_h, out_stack);
}